// round 4
// baseline (speedup 1.0000x reference)
#include <cuda_runtime.h>
#include <math.h>

// Problem shape (fixed by the dataset)
#define NB   8
#define NC   128
#define NHW  1024
#define NTOT (NB*NHW)      // 8192
#define NCLS 5
#define INV_T 10.0f        // 1/TEMPERATURE, folded into student normalization

#define BM 128             // i-rows per block
#define BN 128             // j-cols per tile
#define KD 128

// ---------------- device scratch (no allocations allowed) ----------------
__device__ float g_s[NTOT*NC];        // student, L2-normalized * (1/T), [N][C]
__device__ float g_t[NTOT*NC];        // teacher, L2-normalized,         [N][C]
__device__ float g_sep[2*NTOT];       // partial sum-of-exp per (half, i); each slot single-writer
__device__ float g_clsum[NCLS*NC];    // per-class sums of teacher rows
__device__ float g_clcnt[NCLS];
__device__ float g_acc[2];            // {sum w*mlpp, sum w}
__device__ int   g_lmode;             // 0 = int32 labels, 1 = int64 labels

// ---------------- helpers ----------------
__device__ __forceinline__ unsigned long long fma2(unsigned long long a,
                                                   unsigned long long b,
                                                   unsigned long long c) {
    unsigned long long d;
    asm("fma.rn.f32x2 %0, %1, %2, %3;" : "=l"(d) : "l"(a), "l"(b), "l"(c));
    return d;
}
__device__ __forceinline__ void cpasync16(unsigned smem, const void* g) {
    asm volatile("cp.async.cg.shared.global [%0], [%1], 16;\n" :: "r"(smem), "l"(g));
}
__device__ __forceinline__ void cpcommit() {
    asm volatile("cp.async.commit_group;\n" ::: "memory");
}
template<int N> __device__ __forceinline__ void cpwait() {
    asm volatile("cp.async.wait_group %0;\n" :: "n"(N) : "memory");
}
__device__ __forceinline__ int get_label(const void* p, int i) {
    if (g_lmode) return (int)(((const long long*)p)[i]);
    return ((const int*)p)[i];
}
// swizzle: chunk slot within a 32-chunk row
__device__ __forceinline__ int swz(int row) { return (row ^ (row >> 3)) & 7; }

// ---------------- K0: label dtype probe ----------------
__global__ void k_detect(const int* sl, const int* tl) {
    if (threadIdx.x == 0) {
        int allzero = 1;
        for (int i = 1; i < 256; i += 2) {
            if (sl[i] != 0 || tl[i] != 0) { allzero = 0; break; }
        }
        g_lmode = allzero;  // int64 storage -> every odd 32-bit word is a zero high-word
    }
}

// ---------------- K1: zero accumulators ----------------
__global__ void k_zero() {
    int t = threadIdx.x;
    if (t < NCLS*NC) g_clsum[t] = 0.f;
    if (t < NCLS)    g_clcnt[t] = 0.f;
    if (t < 2)       g_acc[t]   = 0.f;
}

// ---------------- K2: normalize + transpose ([B,C,HW] -> [N,C]) ----------------
// grid (256, 2): y==0 student (scale 1/T), y==1 teacher. block 256 = 32hw x 8c.
__global__ __launch_bounds__(256) void k_norm(const float* __restrict__ s_in,
                                              const float* __restrict__ t_in) {
    __shared__ float sh[NC][33];
    __shared__ float part[8][32];
    __shared__ float invn[32];
    const float* in  = (blockIdx.y == 0) ? s_in : t_in;
    float*       out = (blockIdx.y == 0) ? g_s  : g_t;
    const float  scale = (blockIdx.y == 0) ? INV_T : 1.0f;
    int b   = blockIdx.x >> 5;
    int hw0 = (blockIdx.x & 31) << 5;
    int tx = threadIdx.x & 31, ty = threadIdx.x >> 5;
    float p = 0.f;
    const float* base = in + (size_t)b * NC * NHW + hw0 + tx;
    for (int c = ty; c < NC; c += 8) {
        float v = base[(size_t)c * NHW];
        sh[c][tx] = v;
        p += v * v;
    }
    part[ty][tx] = p;
    __syncthreads();
    if (ty == 0) {
        float s = 0.f;
        #pragma unroll
        for (int q = 0; q < 8; q++) s += part[q][tx];
        invn[tx] = rsqrtf(s) * scale;
    }
    __syncthreads();
    int n0 = b * NHW + hw0;
    for (int idx = threadIdx.x; idx < NC * 32; idx += 256) {
        int c = idx & 127, q = idx >> 7;
        out[(size_t)(n0 + q) * NC + c] = sh[c][q] * invn[q];
    }
}

// ---------------- K3: per-class teacher sums + counts ----------------
__global__ __launch_bounds__(128) void k_clsum(const void* tl) {
    __shared__ float acc[NCLS][NC];
    __shared__ float cnt[NCLS];
    int tid = threadIdx.x;
    for (int q = tid; q < NCLS*NC; q += 128) ((float*)acc)[q] = 0.f;
    if (tid < NCLS) cnt[tid] = 0.f;
    __syncthreads();
    int base = blockIdx.x * 128;
    for (int r = 0; r < 128; r++) {
        int row = base + r;
        int lbl = get_label(tl, row);
        lbl = min(max(lbl, 0), NCLS - 1);
        acc[lbl][tid] += g_t[(size_t)row * NC + tid];
        if (tid == 0) cnt[lbl] += 1.f;
    }
    __syncthreads();
    for (int q = tid; q < NCLS*NC; q += 128) atomicAdd(&g_clsum[q], ((float*)acc)[q]);
    if (tid < NCLS) atomicAdd(&g_clcnt[tid], cnt[tid]);
}

// ---------------- K4: fused GEMM + exp + row-sum -> partial sum-of-exp ----------------
// grid = 128 blocks: block b handles i-tile (b>>1) x j-half (b&1).
// SMEM layout per tile: row-major [row][32 chunks of 16B], chunk slot swizzled:
//   slot(row,k4) = k4 ^ ((row ^ (row>>3)) & 7)
// -> cp.async stores conflict-free (1 row / warp, all 32 chunk cols);
//    a-reads (rows 8ty+r, 2 rows/warp differing by 8): distinct banks + broadcast -> 1 phase;
//    b-reads (cols 16c+tx, 16 consecutive rows/warp): 8 bank groups x 2-way -> 2 phases (min).
// 8x8 per-thread tile, f32x2 accumulators paired along k.
extern __shared__ float smem3[];

__global__ __launch_bounds__(256, 1) void k_main() {
    float* sA  = smem3;                  // 16384 floats (64KB)
    float* tB0 = smem3 + BM * KD;        // 16384
    float* tB1 = smem3 + 2 * BM * KD;    // 16384
    int tid = threadIdx.x;
    int tx = tid & 15, ty = tid >> 4;
    int i0    = (blockIdx.x >> 1) * BM;
    int half  = blockIdx.x & 1;
    int jbase = half * (NTOT / 2);
    unsigned sA_u  = (unsigned)__cvta_generic_to_shared(sA);
    unsigned tB_u0 = (unsigned)__cvta_generic_to_shared(tB0);
    unsigned tB_u1 = (unsigned)__cvta_generic_to_shared(tB1);

    // prologue: sA (student tile, reused for all j) + teacher tile 0 -> one group
    #pragma unroll
    for (int it = 0; it < 16; it++) {
        int idx = tid + it * 256;
        int row = idx >> 5, k4 = idx & 31;
        int slot = row * 32 + (k4 ^ swz(row));
        cpasync16(sA_u + slot * 16, g_s + (size_t)(i0 + row) * KD + k4 * 4);
    }
    #pragma unroll
    for (int it = 0; it < 16; it++) {
        int idx = tid + it * 256;
        int col = idx >> 5, k4 = idx & 31;
        int slot = col * 32 + (k4 ^ swz(col));
        cpasync16(tB_u0 + slot * 16, g_t + (size_t)(jbase + col) * KD + k4 * 4);
    }
    cpcommit();

    // per-thread row/col swizzle constants
    int swa[8], swb[8];
    #pragma unroll
    for (int r = 0; r < 8; r++) swa[r] = swz(8 * ty + r);
    #pragma unroll
    for (int c = 0; c < 8; c++) swb[c] = swz(16 * c + tx);

    float rs[8];
    #pragma unroll
    for (int r = 0; r < 8; r++) rs[r] = 0.f;

    const int NT = (NTOT / 2) / BN;  // 32 tiles
    for (int jt = 0; jt < NT; jt++) {
        if (jt + 1 < NT) {
            int j0 = jbase + (jt + 1) * BN;
            unsigned dstb = ((jt + 1) & 1) ? tB_u1 : tB_u0;
            #pragma unroll
            for (int it = 0; it < 16; it++) {
                int idx = tid + it * 256;
                int col = idx >> 5, k4 = idx & 31;
                int slot = col * 32 + (k4 ^ swz(col));
                cpasync16(dstb + slot * 16, g_t + (size_t)(j0 + col) * KD + k4 * 4);
            }
            cpcommit();
            cpwait<1>();   // current tile's group complete; next tile in flight
        } else {
            cpwait<0>();
        }
        __syncthreads();

        const float* tb = (jt & 1) ? tB1 : tB0;
        unsigned long long acc[8][8];
        #pragma unroll
        for (int r = 0; r < 8; r++)
            #pragma unroll
            for (int c = 0; c < 8; c++) acc[r][c] = 0ull;

        #pragma unroll 4
        for (int k4 = 0; k4 < 32; k4++) {
            ulonglong2 a2[8], b2[8];
            #pragma unroll
            for (int r = 0; r < 8; r++)
                a2[r] = *(const ulonglong2*)(sA + (size_t)((8 * ty + r) * 32 + (k4 ^ swa[r])) * 4);
            #pragma unroll
            for (int c = 0; c < 8; c++)
                b2[c] = *(const ulonglong2*)(tb + (size_t)((16 * c + tx) * 32 + (k4 ^ swb[c])) * 4);
            #pragma unroll
            for (int r = 0; r < 8; r++)
                #pragma unroll
                for (int c = 0; c < 8; c++) {
                    acc[r][c] = fma2(a2[r].x, b2[c].x, acc[r][c]);
                    acc[r][c] = fma2(a2[r].y, b2[c].y, acc[r][c]);
                }
        }
        // exp + row accumulate (|logit| <= 10 -> no max pass needed, fp32 safe)
        #pragma unroll
        for (int r = 0; r < 8; r++) {
            float e = 0.f;
            #pragma unroll
            for (int c = 0; c < 8; c++) {
                unsigned long long v = acc[r][c];
                float lo = __uint_as_float((unsigned)v);
                float hi = __uint_as_float((unsigned)(v >> 32));
                e += __expf(lo + hi);
            }
            rs[r] += e;
        }
        __syncthreads();   // protects buffer reuse for next iteration's cp.async
    }

    // reduce 16 tx-partials per row (alias sA; safe after final barrier above)
    float* red = sA;  // 128 x 17
    #pragma unroll
    for (int r = 0; r < 8; r++) red[(8 * ty + r) * 17 + tx] = rs[r];
    __syncthreads();
    if (tid < BM) {
        float s = 0.f;
        #pragma unroll
        for (int x = 0; x < 16; x++) s += red[tid * 17 + x];
        g_sep[half * NTOT + i0 + tid] = s;   // single writer per slot: deterministic
    }
}

// ---------------- K5: per-anchor terms + reduction ----------------
__global__ __launch_bounds__(256) void k_final(const void* sl) {
    int i = blockIdx.x * 256 + threadIdx.x;
    int lbl = get_label(sl, i);
    int lc = min(max(lbl, 0), NCLS - 1);
    float cnt = g_clcnt[lc];
    float lse = logf(g_sep[i] + g_sep[NTOT + i]);
    const float4* sv = (const float4*)(g_s + (size_t)i * NC);
    const float4* cv = (const float4*)(g_clsum + lc * NC);
    float dot = 0.f;   // = sum_{j: tl_j == lbl} logit(i,j)   (1/T already folded into g_s)
    #pragma unroll
    for (int q = 0; q < 32; q++) {
        float4 a = sv[q], b = cv[q];
        dot += a.x * b.x + a.y * b.y + a.z * b.z + a.w * b.w;
    }
    float mlpp = (dot - cnt * lse) / (cnt + 1e-8f);
    float w = (cnt > 1e-8f && lbl != 0) ? 1.f : 0.f;

    __shared__ float r1[256], r2[256];
    r1[threadIdx.x] = w * mlpp;
    r2[threadIdx.x] = w;
    __syncthreads();
    for (int s = 128; s > 0; s >>= 1) {
        if (threadIdx.x < s) {
            r1[threadIdx.x] += r1[threadIdx.x + s];
            r2[threadIdx.x] += r2[threadIdx.x + s];
        }
        __syncthreads();
    }
    if (threadIdx.x == 0) {
        atomicAdd(&g_acc[0], r1[0]);
        atomicAdd(&g_acc[1], r2[0]);
    }
}

__global__ void k_loss(float* out) {
    out[0] = -g_acc[0] / g_acc[1];
}

// ---------------- launch ----------------
extern "C" void kernel_launch(void* const* d_in, const int* in_sizes, int n_in,
                              void* d_out, int out_size) {
    const float* s_in = (const float*)d_in[0];
    const float* t_in = (const float*)d_in[1];
    const void*  sl   = d_in[2];
    const void*  tl   = d_in[3];
    float* out = (float*)d_out;

    cudaFuncSetAttribute(k_main, cudaFuncAttributeMaxDynamicSharedMemorySize,
                         3 * BM * KD * (int)sizeof(float));

    k_detect<<<1, 32>>>((const int*)sl, (const int*)tl);
    k_zero<<<1, 640>>>();
    k_norm<<<dim3(256, 2), 256>>>(s_in, t_in);
    k_clsum<<<NTOT / 128, 128>>>(tl);
    k_main<<<(NTOT / BM) * 2, 256, 3 * BM * KD * sizeof(float)>>>();
    k_final<<<NTOT / 256, 256>>>(sl);
    k_loss<<<1, 1>>>(out);
}